// round 1
// baseline (speedup 1.0000x reference)
#include <cuda_runtime.h>
#include <math_constants.h>

#define BB   2
#define TT   2048
#define KD   1024
#define NH   16
#define HD   64
#define MTOT (BB*TT)

// Scratch (allocation-free rule: __device__ globals)
__device__ float g_q[(size_t)MTOT * KD];
__device__ float g_k[(size_t)MTOT * KD];
__device__ float g_v[(size_t)MTOT * KD];
__device__ float g_o[(size_t)MTOT * KD];

// ---------------------------------------------------------------------------
// Tiled SGEMM body: C[m,n] = scale * sum_k A[m,k] * W[n,k] (+ bias[n])
// BM=BN=128, BK=16, 256 threads, 8x8 per thread (two 4x4 blocks per axis).
// ---------------------------------------------------------------------------
__device__ __forceinline__ void gemm_body(
    const float* __restrict__ A, const float* __restrict__ W,
    const float* __restrict__ bias, float* __restrict__ C, float scale)
{
    __shared__ float As[16][132];   // transposed: As[k][m], +4 pad
    __shared__ float Bs[16][132];   // transposed: Bs[k][n]

    const int tid  = threadIdx.x;
    const int m0   = blockIdx.y * 128;
    const int n0   = blockIdx.x * 128;
    const int trow = tid >> 4;      // 0..15
    const int tcol = tid & 15;      // 0..15

    float acc[8][8];
#pragma unroll
    for (int i = 0; i < 8; i++)
#pragma unroll
        for (int j = 0; j < 8; j++) acc[i][j] = 0.f;

    for (int k0 = 0; k0 < KD; k0 += 16) {
#pragma unroll
        for (int i = 0; i < 2; i++) {
            int idx = tid + i * 256;          // 0..511 float4 slots
            int r   = idx >> 2;               // 0..127
            int c4  = (idx & 3) << 2;         // 0,4,8,12
            float4 a = *(const float4*)(A + (size_t)(m0 + r) * KD + k0 + c4);
            As[c4+0][r] = a.x; As[c4+1][r] = a.y; As[c4+2][r] = a.z; As[c4+3][r] = a.w;
            float4 b = *(const float4*)(W + (size_t)(n0 + r) * KD + k0 + c4);
            Bs[c4+0][r] = b.x; Bs[c4+1][r] = b.y; Bs[c4+2][r] = b.z; Bs[c4+3][r] = b.w;
        }
        __syncthreads();
#pragma unroll
        for (int kk = 0; kk < 16; kk++) {
            float4 a0 = *(const float4*)&As[kk][trow * 4];
            float4 a1 = *(const float4*)&As[kk][trow * 4 + 64];
            float4 b0 = *(const float4*)&Bs[kk][tcol * 4];
            float4 b1 = *(const float4*)&Bs[kk][tcol * 4 + 64];
            float av[8] = {a0.x, a0.y, a0.z, a0.w, a1.x, a1.y, a1.z, a1.w};
            float bv[8] = {b0.x, b0.y, b0.z, b0.w, b1.x, b1.y, b1.z, b1.w};
#pragma unroll
            for (int i = 0; i < 8; i++)
#pragma unroll
                for (int j = 0; j < 8; j++)
                    acc[i][j] = fmaf(av[i], bv[j], acc[i][j]);
        }
        __syncthreads();
    }

    float bvals[8];
#pragma unroll
    for (int j = 0; j < 8; j++) {
        int c = n0 + tcol * 4 + (j & 3) + ((j >> 2) << 6);
        bvals[j] = bias ? bias[c] : 0.f;
    }
#pragma unroll
    for (int i = 0; i < 8; i++) {
        int r = m0 + trow * 4 + (i & 3) + ((i >> 2) << 6);
        float4 o0, o1;
        o0.x = fmaf(acc[i][0], scale, bvals[0]);
        o0.y = fmaf(acc[i][1], scale, bvals[1]);
        o0.z = fmaf(acc[i][2], scale, bvals[2]);
        o0.w = fmaf(acc[i][3], scale, bvals[3]);
        o1.x = fmaf(acc[i][4], scale, bvals[4]);
        o1.y = fmaf(acc[i][5], scale, bvals[5]);
        o1.z = fmaf(acc[i][6], scale, bvals[6]);
        o1.w = fmaf(acc[i][7], scale, bvals[7]);
        *(float4*)(C + (size_t)r * KD + n0 + tcol * 4)      = o0;
        *(float4*)(C + (size_t)r * KD + n0 + tcol * 4 + 64) = o1;
    }
}

__global__ __launch_bounds__(256) void qkv_gemm(
    const float* __restrict__ x,
    const float* __restrict__ Wq, const float* __restrict__ Wk,
    const float* __restrict__ Wv)
{
    const float inv_s = 0.17677669529663687f;  // 1024^(-1/4)
    if (blockIdx.z == 0)      gemm_body(x, Wq, nullptr, g_q, inv_s);
    else if (blockIdx.z == 1) gemm_body(x, Wk, nullptr, g_k, inv_s);
    else                      gemm_body(x, Wv, nullptr, g_v, 1.0f);
}

__global__ __launch_bounds__(256) void out_gemm(
    const float* __restrict__ Wu, const float* __restrict__ bu,
    float* __restrict__ out)
{
    gemm_body(g_o, Wu, bu, out, 1.0f);
}

// ---------------------------------------------------------------------------
// Flash attention: one CTA per (q-block of 64 rows, head, batch).
// Br=Bc=64, d=64. Online softmax. K smem tile aliased by P tile.
// ---------------------------------------------------------------------------
#define SSTRIDE 68

__global__ __launch_bounds__(256) void attn_kernel()
{
    extern __shared__ float sm[];
    float* Qst = sm;                         // Q^T [d][r], stride 68
    float* KPs = sm + 64 * SSTRIDE;          // K^T [d][c]  (reused as P [r][c])
    float* Vs  = sm + 2 * 64 * SSTRIDE;      // V   [c][d]

    const int tid = threadIdx.x;
    const int ty  = tid >> 4;   // 0..15 -> rows ty*4..+3
    const int tx  = tid & 15;   // 0..15 -> cols/dims tx*4..+3
    const int qb  = blockIdx.x;
    const int h   = blockIdx.y;
    const int b   = blockIdx.z;

    const size_t head_off = (size_t)h * HD;

    // Load Q tile transposed
#pragma unroll
    for (int i = 0; i < 4; i++) {
        int lin = tid + i * 256;       // 0..1023 (16 float4 per row)
        int r   = lin >> 4;
        int d4  = (lin & 15) << 2;
        float4 q = *(const float4*)(g_q + (size_t)(b * TT + qb * 64 + r) * KD + head_off + d4);
        Qst[(d4+0) * SSTRIDE + r] = q.x;
        Qst[(d4+1) * SSTRIDE + r] = q.y;
        Qst[(d4+2) * SSTRIDE + r] = q.z;
        Qst[(d4+3) * SSTRIDE + r] = q.w;
    }

    float m_r[4], l_r[4], o_acc[4][4];
#pragma unroll
    for (int i = 0; i < 4; i++) {
        m_r[i] = -CUDART_INF_F;
        l_r[i] = 0.f;
#pragma unroll
        for (int j = 0; j < 4; j++) o_acc[i][j] = 0.f;
    }

    for (int jb = 0; jb < TT / 64; jb++) {
        __syncthreads();   // previous P reads done; safe to overwrite KPs/Vs
#pragma unroll
        for (int i = 0; i < 4; i++) {
            int lin = tid + i * 256;
            int r   = lin >> 4;
            int d4  = (lin & 15) << 2;
            size_t tok = (size_t)(b * TT + jb * 64 + r);
            float4 kq = *(const float4*)(g_k + tok * KD + head_off + d4);
            KPs[(d4+0) * SSTRIDE + r] = kq.x;
            KPs[(d4+1) * SSTRIDE + r] = kq.y;
            KPs[(d4+2) * SSTRIDE + r] = kq.z;
            KPs[(d4+3) * SSTRIDE + r] = kq.w;
            float4 vv = *(const float4*)(g_v + tok * KD + head_off + d4);
            *(float4*)&Vs[r * SSTRIDE + d4] = vv;
        }
        __syncthreads();

        // S = Q K^T (64x64, 4x4 per thread)
        float s[4][4];
#pragma unroll
        for (int i = 0; i < 4; i++)
#pragma unroll
            for (int j = 0; j < 4; j++) s[i][j] = 0.f;
#pragma unroll
        for (int kk = 0; kk < 64; kk++) {
            float4 qv = *(const float4*)&Qst[kk * SSTRIDE + ty * 4];
            float4 kv = *(const float4*)&KPs[kk * SSTRIDE + tx * 4];
            float qa[4] = {qv.x, qv.y, qv.z, qv.w};
            float ka[4] = {kv.x, kv.y, kv.z, kv.w};
#pragma unroll
            for (int i = 0; i < 4; i++)
#pragma unroll
                for (int j = 0; j < 4; j++)
                    s[i][j] = fmaf(qa[i], ka[j], s[i][j]);
        }

        // Online softmax update (row reductions across the 16 tx lanes)
#pragma unroll
        for (int i = 0; i < 4; i++) {
            float mx = fmaxf(fmaxf(s[i][0], s[i][1]), fmaxf(s[i][2], s[i][3]));
#pragma unroll
            for (int off = 8; off; off >>= 1)
                mx = fmaxf(mx, __shfl_xor_sync(0xffffffffu, mx, off));
            float m_new = fmaxf(m_r[i], mx);
            float corr  = __expf(m_r[i] - m_new);
            float rs = 0.f;
#pragma unroll
            for (int j = 0; j < 4; j++) {
                s[i][j] = __expf(s[i][j] - m_new);
                rs += s[i][j];
            }
#pragma unroll
            for (int off = 8; off; off >>= 1)
                rs += __shfl_xor_sync(0xffffffffu, rs, off);
            l_r[i] = l_r[i] * corr + rs;
            m_r[i] = m_new;
#pragma unroll
            for (int j = 0; j < 4; j++) o_acc[i][j] *= corr;
        }

        __syncthreads();   // all K^T reads done -> reuse as P
#pragma unroll
        for (int i = 0; i < 4; i++)
            *(float4*)&KPs[(ty * 4 + i) * SSTRIDE + tx * 4] =
                make_float4(s[i][0], s[i][1], s[i][2], s[i][3]);
        __syncthreads();

        // O += P V
#pragma unroll 16
        for (int c = 0; c < 64; c++) {
            float4 vv = *(const float4*)&Vs[c * SSTRIDE + tx * 4];
            float va[4] = {vv.x, vv.y, vv.z, vv.w};
#pragma unroll
            for (int i = 0; i < 4; i++) {
                float p = KPs[(ty * 4 + i) * SSTRIDE + c];  // broadcast
#pragma unroll
                for (int j = 0; j < 4; j++)
                    o_acc[i][j] = fmaf(p, va[j], o_acc[i][j]);
            }
        }
    }

    // Normalize and write to g_o as [b,t, h*64+d]
#pragma unroll
    for (int i = 0; i < 4; i++) {
        float inv_l = 1.f / l_r[i];
        float4 o = make_float4(o_acc[i][0] * inv_l, o_acc[i][1] * inv_l,
                               o_acc[i][2] * inv_l, o_acc[i][3] * inv_l);
        *(float4*)(g_o + (size_t)(b * TT + qb * 64 + ty * 4 + i) * KD + head_off + tx * 4) = o;
    }
}

// ---------------------------------------------------------------------------
extern "C" void kernel_launch(void* const* d_in, const int* in_sizes, int n_in,
                              void* d_out, int out_size)
{
    const float* x  = (const float*)d_in[0];
    const float* Wq = (const float*)d_in[1];
    const float* Wk = (const float*)d_in[2];
    const float* Wv = (const float*)d_in[3];
    const float* Wu = (const float*)d_in[4];
    const float* bu = (const float*)d_in[5];
    float* out = (float*)d_out;

    qkv_gemm<<<dim3(KD / 128, MTOT / 128, 3), 256>>>(x, Wq, Wk, Wv);

    const int smem = 3 * 64 * SSTRIDE * (int)sizeof(float);  // 52224 B
    cudaFuncSetAttribute(attn_kernel, cudaFuncAttributeMaxDynamicSharedMemorySize, smem);
    attn_kernel<<<dim3(TT / 64, NH, BB), 256, smem>>>();

    out_gemm<<<dim3(KD / 128, MTOT / 128), 256>>>(Wu, bu, out);
}

// round 3
// speedup vs baseline: 1.2735x; 1.2735x over previous
#include <cuda_runtime.h>
#include <cuda_bf16.h>
#include <math_constants.h>
#include <cstdint>

#define BB   2
#define TT   2048
#define KD   1024
#define NH   16
#define HD   64
#define MTOT (BB*TT)

// ---------------- scratch (__device__ globals, allocation-free) -------------
__device__ float g_q[(size_t)MTOT * KD];
__device__ float g_k[(size_t)MTOT * KD];
__device__ float g_v[(size_t)MTOT * KD];

// split-bf16 operands: [rows][2048] = [hi(1024) | lo(1024)]
__device__ __nv_bfloat16 g_x2 [(size_t)MTOT * 2048];
__device__ __nv_bfloat16 g_wq2[(size_t)KD   * 2048];
__device__ __nv_bfloat16 g_wk2[(size_t)KD   * 2048];
__device__ __nv_bfloat16 g_wv2[(size_t)KD   * 2048];
__device__ __nv_bfloat16 g_wu2[(size_t)KD   * 2048];
__device__ __nv_bfloat16 g_o2 [(size_t)MTOT * 2048];

// ---------------- helpers ----------------------------------------------------
__device__ __forceinline__ uint32_t smem_u32(const void* p) {
    uint32_t a;
    asm("{ .reg .u64 t; cvta.to.shared.u64 t, %1; cvt.u32.u64 %0, t; }"
        : "=r"(a) : "l"(p));
    return a;
}

__device__ __forceinline__ void cp16(uint32_t dst, const void* src) {
    asm volatile("cp.async.cg.shared.global [%0], [%1], 16;" :: "r"(dst), "l"(src));
}
__device__ __forceinline__ void cp_commit() {
    asm volatile("cp.async.commit_group;" ::: "memory");
}
template <int N>
__device__ __forceinline__ void cp_wait() {
    asm volatile("cp.async.wait_group %0;" :: "n"(N) : "memory");
}

__device__ __forceinline__ void ldm_x4(uint32_t* r, uint32_t addr) {
    asm volatile("ldmatrix.sync.aligned.m8n8.x4.shared.b16 {%0,%1,%2,%3}, [%4];"
                 : "=r"(r[0]), "=r"(r[1]), "=r"(r[2]), "=r"(r[3]) : "r"(addr));
}

__device__ __forceinline__ void mma_bf16(float* c, const uint32_t* a, const uint32_t* b) {
    asm volatile(
        "mma.sync.aligned.m16n8k16.row.col.f32.bf16.bf16.f32 "
        "{%0,%1,%2,%3}, {%4,%5,%6,%7}, {%8,%9}, {%0,%1,%2,%3};"
        : "+f"(c[0]), "+f"(c[1]), "+f"(c[2]), "+f"(c[3])
        : "r"(a[0]), "r"(a[1]), "r"(a[2]), "r"(a[3]), "r"(b[0]), "r"(b[1]));
}

// ---------------- split conversion: fp32 row-1024 -> bf16 hi|lo row-2048 ----
__global__ void split_kernel(const float* __restrict__ in, int which) {
    __nv_bfloat16* out =
        which == 0 ? g_x2  :
        which == 1 ? g_wq2 :
        which == 2 ? g_wk2 :
        which == 3 ? g_wv2 : g_wu2;
    int r = blockIdx.x;
    int c = threadIdx.x * 4;
    float4 a = *(const float4*)(in + (size_t)r * KD + c);
    float av[4] = {a.x, a.y, a.z, a.w};
    __nv_bfloat16 h[4], l[4];
#pragma unroll
    for (int i = 0; i < 4; i++) {
        h[i] = __float2bfloat16(av[i]);
        l[i] = __float2bfloat16(av[i] - __bfloat162float(h[i]));
    }
    __nv_bfloat16* oh = out + (size_t)r * 2048 + c;
    *(__nv_bfloat162*)(oh)          = __halves2bfloat162(h[0], h[1]);
    *(__nv_bfloat162*)(oh + 2)      = __halves2bfloat162(h[2], h[3]);
    *(__nv_bfloat162*)(oh + 1024)   = __halves2bfloat162(l[0], l[1]);
    *(__nv_bfloat162*)(oh + 1026)   = __halves2bfloat162(l[2], l[3]);
}

// ---------------- mma.sync split-bf16 GEMM -----------------------------------
// C[m,n] = scale * sum_k A[m,k]*W[n,k] (+ bias[n])
// K_ext = 3072 over combos (Ah,Wh), (Al,Wh), (Ah,Wl).  CTA tile 128x128, BK=32.
#define GSTRIDE 40            // padded bf16 row stride in smem
#define STAGE_B (128 * GSTRIDE * 2)   // 10240 bytes per tile
#define SMEM_MMA (4 * STAGE_B)        // A0,B0,A1,B1 = 40960

__device__ __forceinline__ void load_stage(
    const __nv_bfloat16* __restrict__ Ag, const __nv_bfloat16* __restrict__ Wg,
    uint32_t sA, uint32_t sB, int tid)
{
#pragma unroll
    for (int i = 0; i < 2; i++) {
        int c = tid + i * 256;        // 0..511
        int r = c >> 2;
        int q = c & 3;
        cp16(sA + r * (GSTRIDE * 2) + q * 16, Ag + (size_t)r * 2048 + q * 8);
        cp16(sB + r * (GSTRIDE * 2) + q * 16, Wg + (size_t)r * 2048 + q * 8);
    }
}

__device__ __forceinline__ void tgemm_mma(
    const __nv_bfloat16* __restrict__ A2, const __nv_bfloat16* __restrict__ W2,
    float* __restrict__ C, float scale, const float* __restrict__ bias)
{
    extern __shared__ char sm[];
    const uint32_t smb = smem_u32(sm);
    const int tid    = threadIdx.x;
    const int lane   = tid & 31;
    const int wid    = tid >> 5;
    const int warp_m = wid & 1;       // 2 warps along M (64 each)
    const int warp_n = wid >> 1;      // 4 warps along N (32 each)
    const int m0     = blockIdx.y * 128;
    const int n0     = blockIdx.x * 128;

    const __nv_bfloat16* Abase = A2 + (size_t)m0 * 2048;
    const __nv_bfloat16* Wbase = W2 + (size_t)n0 * 2048;

    float acc[4][4][4];
#pragma unroll
    for (int i = 0; i < 4; i++)
#pragma unroll
        for (int j = 0; j < 4; j++)
#pragma unroll
            for (int r = 0; r < 4; r++) acc[i][j][r] = 0.f;

    const int NIT = 96;               // 3 combos * 32 k-iters
    const int aoffs[3] = {0, 1024, 0};
    const int woffs[3] = {0, 0, 1024};

    // prologue: stage 0
    load_stage(Abase + aoffs[0] + 0, Wbase + woffs[0] + 0,
               smb, smb + STAGE_B, tid);
    cp_commit();

    // ldmatrix lane address components (element offsets within tile rows)
    const int a_row = (lane & 15);
    const int a_col = (lane >> 4) << 3;               // 0 or 8
    const int b_row = ((lane >> 4) << 3) + (lane & 7);
    const int b_col = ((lane >> 3) & 1) << 3;         // 0 or 8

    for (int it = 0; it < NIT; it++) {
        const int s = it & 1;
        if (it + 1 < NIT) {
            const int nx = it + 1;
            const int cb = nx >> 5;
            const int kk = (nx & 31) * 32;
            load_stage(Abase + aoffs[cb] + kk, Wbase + woffs[cb] + kk,
                       smb + ((nx & 1) ? 2 : 0) * STAGE_B,
                       smb + ((nx & 1) ? 3 : 1) * STAGE_B, tid);
            cp_commit();
            cp_wait<1>();
        } else {
            cp_wait<0>();
        }
        __syncthreads();

        const uint32_t sA = smb + (s ? 2 : 0) * STAGE_B;
        const uint32_t sB = smb + (s ? 3 : 1) * STAGE_B;

#pragma unroll
        for (int ks = 0; ks < 2; ks++) {
            uint32_t a[4][4], b[2][4];
#pragma unroll
            for (int mi = 0; mi < 4; mi++) {
                uint32_t addr = sA
                    + (warp_m * 64 + mi * 16 + a_row) * (GSTRIDE * 2)
                    + (ks * 16 + a_col) * 2;
                ldm_x4(a[mi], addr);
            }
#pragma unroll
            for (int ni = 0; ni < 2; ni++) {
                uint32_t addr = sB
                    + (warp_n * 32 + ni * 16 + b_row) * (GSTRIDE * 2)
                    + (ks * 16 + b_col) * 2;
                ldm_x4(b[ni], addr);
            }
#pragma unroll
            for (int mi = 0; mi < 4; mi++)
#pragma unroll
                for (int nj = 0; nj < 4; nj++)
                    mma_bf16(acc[mi][nj], a[mi], &b[nj >> 1][(nj & 1) * 2]);
        }
        __syncthreads();
    }

    // epilogue: direct STG (float2 per fragment half-row)
#pragma unroll
    for (int mi = 0; mi < 4; mi++) {
#pragma unroll
        for (int nj = 0; nj < 4; nj++) {
            int row = m0 + warp_m * 64 + mi * 16 + (lane >> 2);
            int col = n0 + warp_n * 32 + nj * 8 + (lane & 3) * 2;
            float b0 = 0.f, b1 = 0.f;
            if (bias) { b0 = bias[col]; b1 = bias[col + 1]; }
            float2 v0 = make_float2(fmaf(acc[mi][nj][0], scale, b0),
                                    fmaf(acc[mi][nj][1], scale, b1));
            float2 v1 = make_float2(fmaf(acc[mi][nj][2], scale, b0),
                                    fmaf(acc[mi][nj][3], scale, b1));
            *(float2*)(C + (size_t)row * KD + col)       = v0;
            *(float2*)(C + (size_t)(row + 8) * KD + col) = v1;
        }
    }
}

__global__ __launch_bounds__(256, 2) void qkv_mma() {
    const float inv_s = 0.17677669529663687f;   // 1024^(-1/4)
    if (blockIdx.z == 0)      tgemm_mma(g_x2, g_wq2, g_q, inv_s, nullptr);
    else if (blockIdx.z == 1) tgemm_mma(g_x2, g_wk2, g_k, inv_s, nullptr);
    else                      tgemm_mma(g_x2, g_wv2, g_v, 1.0f,  nullptr);
}

__global__ __launch_bounds__(256, 2) void out_mma(const float* __restrict__ bu,
                                                  float* __restrict__ out) {
    tgemm_mma(g_o2, g_wu2, out, 1.0f, bu);
}

// ---------------- SIMT flash attention (proven, unchanged core) --------------
#define SSTRIDE 68

__global__ __launch_bounds__(256) void attn_kernel()
{
    extern __shared__ float smf[];
    float* Qst = smf;
    float* KPs = smf + 64 * SSTRIDE;
    float* Vs  = smf + 2 * 64 * SSTRIDE;

    const int tid = threadIdx.x;
    const int ty  = tid >> 4;
    const int tx  = tid & 15;
    const int qb  = blockIdx.x;
    const int h   = blockIdx.y;
    const int b   = blockIdx.z;
    const size_t head_off = (size_t)h * HD;

#pragma unroll
    for (int i = 0; i < 4; i++) {
        int lin = tid + i * 256;
        int r   = lin >> 4;
        int d4  = (lin & 15) << 2;
        float4 q = *(const float4*)(g_q + (size_t)(b * TT + qb * 64 + r) * KD + head_off + d4);
        Qst[(d4+0) * SSTRIDE + r] = q.x;
        Qst[(d4+1) * SSTRIDE + r] = q.y;
        Qst[(d4+2) * SSTRIDE + r] = q.z;
        Qst[(d4+3) * SSTRIDE + r] = q.w;
    }

    float m_r[4], l_r[4], o_acc[4][4];
#pragma unroll
    for (int i = 0; i < 4; i++) {
        m_r[i] = -CUDART_INF_F;
        l_r[i] = 0.f;
#pragma unroll
        for (int j = 0; j < 4; j++) o_acc[i][j] = 0.f;
    }

    for (int jb = 0; jb < TT / 64; jb++) {
        __syncthreads();
#pragma unroll
        for (int i = 0; i < 4; i++) {
            int lin = tid + i * 256;
            int r   = lin >> 4;
            int d4  = (lin & 15) << 2;
            size_t tok = (size_t)(b * TT + jb * 64 + r);
            float4 kq = *(const float4*)(g_k + tok * KD + head_off + d4);
            KPs[(d4+0) * SSTRIDE + r] = kq.x;
            KPs[(d4+1) * SSTRIDE + r] = kq.y;
            KPs[(d4+2) * SSTRIDE + r] = kq.z;
            KPs[(d4+3) * SSTRIDE + r] = kq.w;
            float4 vv = *(const float4*)(g_v + tok * KD + head_off + d4);
            *(float4*)&Vs[r * SSTRIDE + d4] = vv;
        }
        __syncthreads();

        float s[4][4];
#pragma unroll
        for (int i = 0; i < 4; i++)
#pragma unroll
            for (int j = 0; j < 4; j++) s[i][j] = 0.f;
#pragma unroll
        for (int kk = 0; kk < 64; kk++) {
            float4 qv = *(const float4*)&Qst[kk * SSTRIDE + ty * 4];
            float4 kv = *(const float4*)&KPs[kk * SSTRIDE + tx * 4];
            float qa[4] = {qv.x, qv.y, qv.z, qv.w};
            float ka[4] = {kv.x, kv.y, kv.z, kv.w};
#pragma unroll
            for (int i = 0; i < 4; i++)
#pragma unroll
                for (int j = 0; j < 4; j++)
                    s[i][j] = fmaf(qa[i], ka[j], s[i][j]);
        }

#pragma unroll
        for (int i = 0; i < 4; i++) {
            float mx = fmaxf(fmaxf(s[i][0], s[i][1]), fmaxf(s[i][2], s[i][3]));
#pragma unroll
            for (int off = 8; off; off >>= 1)
                mx = fmaxf(mx, __shfl_xor_sync(0xffffffffu, mx, off));
            float m_new = fmaxf(m_r[i], mx);
            float corr  = __expf(m_r[i] - m_new);
            float rs = 0.f;
#pragma unroll
            for (int j = 0; j < 4; j++) {
                s[i][j] = __expf(s[i][j] - m_new);
                rs += s[i][j];
            }
#pragma unroll
            for (int off = 8; off; off >>= 1)
                rs += __shfl_xor_sync(0xffffffffu, rs, off);
            l_r[i] = l_r[i] * corr + rs;
            m_r[i] = m_new;
#pragma unroll
            for (int j = 0; j < 4; j++) o_acc[i][j] *= corr;
        }

        __syncthreads();
#pragma unroll
        for (int i = 0; i < 4; i++)
            *(float4*)&KPs[(ty * 4 + i) * SSTRIDE + tx * 4] =
                make_float4(s[i][0], s[i][1], s[i][2], s[i][3]);
        __syncthreads();

#pragma unroll 16
        for (int c = 0; c < 64; c++) {
            float4 vv = *(const float4*)&Vs[c * SSTRIDE + tx * 4];
            float va[4] = {vv.x, vv.y, vv.z, vv.w};
#pragma unroll
            for (int i = 0; i < 4; i++) {
                float p = KPs[(ty * 4 + i) * SSTRIDE + c];
#pragma unroll
                for (int j = 0; j < 4; j++)
                    o_acc[i][j] = fmaf(p, va[j], o_acc[i][j]);
            }
        }
    }

    // epilogue: normalize, split to bf16 hi/lo, write g_o2 [row][2048]
#pragma unroll
    for (int i = 0; i < 4; i++) {
        float inv_l = 1.f / l_r[i];
        size_t row = (size_t)(b * TT + qb * 64 + ty * 4 + i);
        float o[4];
        __nv_bfloat16 hv[4], lv[4];
#pragma unroll
        for (int j = 0; j < 4; j++) {
            o[j]  = o_acc[i][j] * inv_l;
            hv[j] = __float2bfloat16(o[j]);
            lv[j] = __float2bfloat16(o[j] - __bfloat162float(hv[j]));
        }
        __nv_bfloat16* oh = g_o2 + row * 2048 + head_off + tx * 4;
        *(__nv_bfloat162*)(oh)        = __halves2bfloat162(hv[0], hv[1]);
        *(__nv_bfloat162*)(oh + 2)    = __halves2bfloat162(hv[2], hv[3]);
        *(__nv_bfloat162*)(oh + 1024) = __halves2bfloat162(lv[0], lv[1]);
        *(__nv_bfloat162*)(oh + 1026) = __halves2bfloat162(lv[2], lv[3]);
    }
}

// ---------------------------------------------------------------------------
extern "C" void kernel_launch(void* const* d_in, const int* in_sizes, int n_in,
                              void* d_out, int out_size)
{
    const float* x  = (const float*)d_in[0];
    const float* Wq = (const float*)d_in[1];
    const float* Wk = (const float*)d_in[2];
    const float* Wv = (const float*)d_in[3];
    const float* Wu = (const float*)d_in[4];
    const float* bu = (const float*)d_in[5];
    float* out = (float*)d_out;

    split_kernel<<<MTOT, 256>>>(x,  0);
    split_kernel<<<KD,   256>>>(Wq, 1);
    split_kernel<<<KD,   256>>>(Wk, 2);
    split_kernel<<<KD,   256>>>(Wv, 3);
    split_kernel<<<KD,   256>>>(Wu, 4);

    cudaFuncSetAttribute(qkv_mma, cudaFuncAttributeMaxDynamicSharedMemorySize, SMEM_MMA);
    qkv_mma<<<dim3(KD / 128, MTOT / 128, 3), 256, SMEM_MMA>>>();

    const int smemA = 3 * 64 * SSTRIDE * (int)sizeof(float);
    cudaFuncSetAttribute(attn_kernel, cudaFuncAttributeMaxDynamicSharedMemorySize, smemA);
    attn_kernel<<<dim3(TT / 64, NH, BB), 256, smemA>>>();

    cudaFuncSetAttribute(out_mma, cudaFuncAttributeMaxDynamicSharedMemorySize, SMEM_MMA);
    out_mma<<<dim3(KD / 128, MTOT / 128), 256, SMEM_MMA>>>(bu, out);
}

// round 4
// speedup vs baseline: 2.9965x; 2.3530x over previous
#include <cuda_runtime.h>
#include <cuda_bf16.h>
#include <math_constants.h>
#include <cstdint>

#define BB   2
#define TT   2048
#define KD   1024
#define NH   16
#define HD   64
#define MTOT (BB*TT)

// ---------------- scratch (__device__ globals, allocation-free) -------------
// split-bf16 GEMM operands: [rows][2048] = [hi(1024) | lo(1024)]
__device__ __nv_bfloat16 g_x2 [(size_t)MTOT * 2048];
__device__ __nv_bfloat16 g_wq2[(size_t)KD   * 2048];
__device__ __nv_bfloat16 g_wk2[(size_t)KD   * 2048];
__device__ __nv_bfloat16 g_wv2[(size_t)KD   * 2048];
__device__ __nv_bfloat16 g_wu2[(size_t)KD   * 2048];
__device__ __nv_bfloat16 g_o2 [(size_t)MTOT * 2048];
// attention operands
__device__ __nv_bfloat16 g_qh[(size_t)MTOT * KD];
__device__ __nv_bfloat16 g_kh[(size_t)MTOT * KD];
__device__ __nv_bfloat16 g_vh[(size_t)MTOT * KD];
__device__ __nv_bfloat16 g_vl[(size_t)MTOT * KD];

// ---------------- helpers ----------------------------------------------------
__device__ __forceinline__ uint32_t smem_u32(const void* p) {
    uint32_t a;
    asm("{ .reg .u64 t; cvta.to.shared.u64 t, %1; cvt.u32.u64 %0, t; }"
        : "=r"(a) : "l"(p));
    return a;
}
__device__ __forceinline__ void cp16(uint32_t dst, const void* src) {
    asm volatile("cp.async.cg.shared.global [%0], [%1], 16;" :: "r"(dst), "l"(src));
}
__device__ __forceinline__ void cp_commit() {
    asm volatile("cp.async.commit_group;" ::: "memory");
}
template <int N>
__device__ __forceinline__ void cp_wait() {
    asm volatile("cp.async.wait_group %0;" :: "n"(N) : "memory");
}
__device__ __forceinline__ void ldm_x4(uint32_t* r, uint32_t addr) {
    asm volatile("ldmatrix.sync.aligned.m8n8.x4.shared.b16 {%0,%1,%2,%3}, [%4];"
                 : "=r"(r[0]), "=r"(r[1]), "=r"(r[2]), "=r"(r[3]) : "r"(addr));
}
__device__ __forceinline__ void ldm_x4_t(uint32_t* r, uint32_t addr) {
    asm volatile("ldmatrix.sync.aligned.m8n8.x4.trans.shared.b16 {%0,%1,%2,%3}, [%4];"
                 : "=r"(r[0]), "=r"(r[1]), "=r"(r[2]), "=r"(r[3]) : "r"(addr));
}
__device__ __forceinline__ void mma_bf16(float* c, const uint32_t* a, const uint32_t* b) {
    asm volatile(
        "mma.sync.aligned.m16n8k16.row.col.f32.bf16.bf16.f32 "
        "{%0,%1,%2,%3}, {%4,%5,%6,%7}, {%8,%9}, {%0,%1,%2,%3};"
        : "+f"(c[0]), "+f"(c[1]), "+f"(c[2]), "+f"(c[3])
        : "r"(a[0]), "r"(a[1]), "r"(a[2]), "r"(a[3]), "r"(b[0]), "r"(b[1]));
}
// pack {lo, hi} floats into bf16x2 (element0 = lo)
__device__ __forceinline__ uint32_t pack_bf16x2(float lo, float hi) {
    uint32_t d;
    asm("cvt.rn.bf16x2.f32 %0, %1, %2;" : "=r"(d) : "f"(hi), "f"(lo));
    return d;
}
__device__ __forceinline__ float bf16x2_lo(uint32_t p) { return __uint_as_float(p << 16); }
__device__ __forceinline__ float bf16x2_hi(uint32_t p) { return __uint_as_float(p & 0xFFFF0000u); }

__device__ __forceinline__ uint32_t sw128(uint32_t off) {
    return off ^ ((off >> 3) & 0x70);
}

// ---------------- split conversion: fp32 row-1024 -> bf16 hi|lo row-2048 ----
__global__ void split_kernel(const float* __restrict__ in, int which) {
    __nv_bfloat16* out =
        which == 0 ? g_x2  :
        which == 1 ? g_wq2 :
        which == 2 ? g_wk2 :
        which == 3 ? g_wv2 : g_wu2;
    int r = blockIdx.x;
    int c = threadIdx.x * 4;
    float4 a = *(const float4*)(in + (size_t)r * KD + c);
    float av[4] = {a.x, a.y, a.z, a.w};
    __nv_bfloat16 h[4], l[4];
#pragma unroll
    for (int i = 0; i < 4; i++) {
        h[i] = __float2bfloat16(av[i]);
        l[i] = __float2bfloat16(av[i] - __bfloat162float(h[i]));
    }
    __nv_bfloat16* oh = out + (size_t)r * 2048 + c;
    *(__nv_bfloat162*)(oh)          = __halves2bfloat162(h[0], h[1]);
    *(__nv_bfloat162*)(oh + 2)      = __halves2bfloat162(h[2], h[3]);
    *(__nv_bfloat162*)(oh + 1024)   = __halves2bfloat162(l[0], l[1]);
    *(__nv_bfloat162*)(oh + 1026)   = __halves2bfloat162(l[2], l[3]);
}

// ---------------- mma.sync split-bf16 GEMM -----------------------------------
// C[m,n] = scale * sum_k A[m,k]*W[n,k]
// mode 0: fp32 out + bias;  mode 1: bf16 hi only -> Ch;  mode 2: hi->Ch, lo->Cl
#define GSTRIDE 40
#define STAGE_B (128 * GSTRIDE * 2)
#define SMEM_MMA (4 * STAGE_B)

__device__ __forceinline__ void load_stage(
    const __nv_bfloat16* __restrict__ Ag, const __nv_bfloat16* __restrict__ Wg,
    uint32_t sA, uint32_t sB, int tid)
{
#pragma unroll
    for (int i = 0; i < 2; i++) {
        int c = tid + i * 256;
        int r = c >> 2;
        int q = c & 3;
        cp16(sA + r * (GSTRIDE * 2) + q * 16, Ag + (size_t)r * 2048 + q * 8);
        cp16(sB + r * (GSTRIDE * 2) + q * 16, Wg + (size_t)r * 2048 + q * 8);
    }
}

__device__ __forceinline__ void tgemm_mma(
    const __nv_bfloat16* __restrict__ A2, const __nv_bfloat16* __restrict__ W2,
    float scale, int mode,
    float* __restrict__ Cf, const float* __restrict__ bias,
    __nv_bfloat16* __restrict__ Ch, __nv_bfloat16* __restrict__ Cl)
{
    extern __shared__ char sm[];
    const uint32_t smb = smem_u32(sm);
    const int tid    = threadIdx.x;
    const int lane   = tid & 31;
    const int wid    = tid >> 5;
    const int warp_m = wid & 1;
    const int warp_n = wid >> 1;
    const int m0     = blockIdx.y * 128;
    const int n0     = blockIdx.x * 128;

    const __nv_bfloat16* Abase = A2 + (size_t)m0 * 2048;
    const __nv_bfloat16* Wbase = W2 + (size_t)n0 * 2048;

    float acc[4][4][4];
#pragma unroll
    for (int i = 0; i < 4; i++)
#pragma unroll
        for (int j = 0; j < 4; j++)
#pragma unroll
            for (int r = 0; r < 4; r++) acc[i][j][r] = 0.f;

    const int NIT = 96;
    const int aoffs[3] = {0, 1024, 0};
    const int woffs[3] = {0, 0, 1024};

    load_stage(Abase, Wbase, smb, smb + STAGE_B, tid);
    cp_commit();

    const int a_row = (lane & 15);
    const int a_col = (lane >> 4) << 3;
    const int b_row = ((lane >> 4) << 3) + (lane & 7);
    const int b_col = ((lane >> 3) & 1) << 3;

    for (int it = 0; it < NIT; it++) {
        const int s = it & 1;
        if (it + 1 < NIT) {
            const int nx = it + 1;
            const int cb = nx >> 5;
            const int kk = (nx & 31) * 32;
            load_stage(Abase + aoffs[cb] + kk, Wbase + woffs[cb] + kk,
                       smb + ((nx & 1) ? 2 : 0) * STAGE_B,
                       smb + ((nx & 1) ? 3 : 1) * STAGE_B, tid);
            cp_commit();
            cp_wait<1>();
        } else {
            cp_wait<0>();
        }
        __syncthreads();

        const uint32_t sA = smb + (s ? 2 : 0) * STAGE_B;
        const uint32_t sB = smb + (s ? 3 : 1) * STAGE_B;

#pragma unroll
        for (int ks = 0; ks < 2; ks++) {
            uint32_t a[4][4], b[2][4];
#pragma unroll
            for (int mi = 0; mi < 4; mi++)
                ldm_x4(a[mi], sA + (warp_m * 64 + mi * 16 + a_row) * (GSTRIDE * 2)
                              + (ks * 16 + a_col) * 2);
#pragma unroll
            for (int ni = 0; ni < 2; ni++)
                ldm_x4(b[ni], sB + (warp_n * 32 + ni * 16 + b_row) * (GSTRIDE * 2)
                              + (ks * 16 + b_col) * 2);
#pragma unroll
            for (int mi = 0; mi < 4; mi++)
#pragma unroll
                for (int nj = 0; nj < 4; nj++)
                    mma_bf16(acc[mi][nj], a[mi], &b[nj >> 1][(nj & 1) * 2]);
        }
        __syncthreads();
    }

#pragma unroll
    for (int mi = 0; mi < 4; mi++) {
#pragma unroll
        for (int nj = 0; nj < 4; nj++) {
            int row = m0 + warp_m * 64 + mi * 16 + (lane >> 2);
            int col = n0 + warp_n * 32 + nj * 8 + (lane & 3) * 2;
            float v00 = acc[mi][nj][0] * scale, v01 = acc[mi][nj][1] * scale;
            float v10 = acc[mi][nj][2] * scale, v11 = acc[mi][nj][3] * scale;
            if (mode == 0) {
                float b0 = bias[col], b1 = bias[col + 1];
                *(float2*)(Cf + (size_t)row * KD + col)       = make_float2(v00 + b0, v01 + b1);
                *(float2*)(Cf + (size_t)(row + 8) * KD + col) = make_float2(v10 + b0, v11 + b1);
            } else {
                uint32_t h0 = pack_bf16x2(v00, v01);
                uint32_t h1 = pack_bf16x2(v10, v11);
                *(uint32_t*)(Ch + (size_t)row * KD + col)       = h0;
                *(uint32_t*)(Ch + (size_t)(row + 8) * KD + col) = h1;
                if (mode == 2) {
                    uint32_t l0 = pack_bf16x2(v00 - bf16x2_lo(h0), v01 - bf16x2_hi(h0));
                    uint32_t l1 = pack_bf16x2(v10 - bf16x2_lo(h1), v11 - bf16x2_hi(h1));
                    *(uint32_t*)(Cl + (size_t)row * KD + col)       = l0;
                    *(uint32_t*)(Cl + (size_t)(row + 8) * KD + col) = l1;
                }
            }
        }
    }
}

__global__ __launch_bounds__(256, 2) void qkv_mma() {
    const float inv_s = 0.17677669529663687f;   // 1024^(-1/4)
    if (blockIdx.z == 0)
        tgemm_mma(g_x2, g_wq2, inv_s, 1, nullptr, nullptr, g_qh, nullptr);
    else if (blockIdx.z == 1)
        tgemm_mma(g_x2, g_wk2, inv_s, 1, nullptr, nullptr, g_kh, nullptr);
    else
        tgemm_mma(g_x2, g_wv2, 1.0f, 2, nullptr, nullptr, g_vh, g_vl);
}

__global__ __launch_bounds__(256, 2) void out_mma(const float* __restrict__ bu,
                                                  float* __restrict__ out) {
    tgemm_mma(g_o2, g_wu2, 1.0f, 0, out, bu, nullptr, nullptr);
}

// ---------------- tensorized flash attention ---------------------------------
// CTA: 64 q-rows x (head, batch). 4 warps, 16 rows each, full 128 S-cols/warp.
// S = Qh*Kh^T (single bf16); P split hi/lo; O += Ph*Vh + Pl*Vh + Ph*Vl.
#define ATT_SMEM (8192 + 2 * 49152)   // Q (8K) + 2 stages of (K 16K, Vh 16K, Vl 16K)

__global__ __launch_bounds__(128, 2) void attn_mma()
{
    extern __shared__ char sm[];
    const uint32_t smb = smem_u32(sm);
    const int tid = threadIdx.x, lane = tid & 31, w = tid >> 5;
    const int qb = blockIdx.x, h = blockIdx.y, b = blockIdx.z;

    const __nv_bfloat16* Qg  = g_qh + (size_t)(b * TT + qb * 64) * KD + h * HD;
    const __nv_bfloat16* Kg  = g_kh + (size_t)(b * TT) * KD + h * HD;
    const __nv_bfloat16* Vhg = g_vh + (size_t)(b * TT) * KD + h * HD;
    const __nv_bfloat16* Vlg = g_vl + (size_t)(b * TT) * KD + h * HD;

    const uint32_t sQ = smb;

    // Q: 64 rows x 128B = 512 chunks
#pragma unroll
    for (int i = 0; i < 4; i++) {
        int c = tid + i * 128, r = c >> 3, q = c & 7;
        cp16(sQ + sw128(r * 128 + q * 16), Qg + (size_t)r * KD + q * 8);
    }
    // stage 0 (jb=0): K, Vh, Vl: 128 rows x 8 chunks each
    {
        uint32_t sK = smb + 8192;
#pragma unroll
        for (int i = 0; i < 8; i++) {
            int c = tid + i * 128, r = c >> 3, q = c & 7;
            uint32_t so = sw128(r * 128 + q * 16);
            size_t   go = (size_t)r * KD + q * 8;
            cp16(sK + so,         Kg  + go);
            cp16(sK + 16384 + so, Vhg + go);
            cp16(sK + 32768 + so, Vlg + go);
        }
    }
    cp_commit();

    float oacc[8][4];
#pragma unroll
    for (int f = 0; f < 8; f++)
#pragma unroll
        for (int r = 0; r < 4; r++) oacc[f][r] = 0.f;
    float m0 = -CUDART_INF_F, m1 = -CUDART_INF_F, l0 = 0.f, l1 = 0.f;
    uint32_t qa[4][4];

    for (int jb = 0; jb < TT / 128; jb++) {
        cp_wait<0>();
        __syncthreads();

        if (jb + 1 < TT / 128) {
            uint32_t sK = smb + 8192 + ((jb + 1) & 1) * 49152;
            size_t base = (size_t)(jb + 1) * 128;
#pragma unroll
            for (int i = 0; i < 8; i++) {
                int c = tid + i * 128, r = c >> 3, q = c & 7;
                uint32_t so = sw128(r * 128 + q * 16);
                size_t   go = (base + r) * KD + q * 8;
                cp16(sK + so,         Kg  + go);
                cp16(sK + 16384 + so, Vhg + go);
                cp16(sK + 32768 + so, Vlg + go);
            }
            cp_commit();
        }

        if (jb == 0) {
#pragma unroll
            for (int ks = 0; ks < 4; ks++) {
                int ar = w * 16 + (lane & 15);
                int ac = ks * 16 + ((lane >> 4) << 3);
                ldm_x4(qa[ks], sQ + sw128(ar * 128 + ac * 2));
            }
        }

        const uint32_t sK  = smb + 8192 + (jb & 1) * 49152;
        const uint32_t sVh = sK + 16384;
        const uint32_t sVl = sK + 32768;

        // ---- S = Qh * Kh^T (16 rows x 128 cols per warp) ----
        float sacc[16][4];
#pragma unroll
        for (int j = 0; j < 16; j++)
#pragma unroll
            for (int r = 0; r < 4; r++) sacc[j][r] = 0.f;

#pragma unroll
        for (int ks = 0; ks < 4; ks++) {
#pragma unroll
            for (int jn = 0; jn < 8; jn++) {
                uint32_t kb[4];
                int br = jn * 16 + ((lane >> 4) << 3) + (lane & 7);
                int bc = ks * 16 + (((lane >> 3) & 1) << 3);
                ldm_x4(kb, sK + sw128(br * 128 + bc * 2));
                mma_bf16(sacc[2 * jn],     qa[ks], kb);
                mma_bf16(sacc[2 * jn + 1], qa[ks], kb + 2);
            }
        }

        // ---- online softmax ----
        float tm0 = -CUDART_INF_F, tm1 = -CUDART_INF_F;
#pragma unroll
        for (int j = 0; j < 16; j++) {
            tm0 = fmaxf(tm0, fmaxf(sacc[j][0], sacc[j][1]));
            tm1 = fmaxf(tm1, fmaxf(sacc[j][2], sacc[j][3]));
        }
        tm0 = fmaxf(tm0, __shfl_xor_sync(0xffffffffu, tm0, 1));
        tm0 = fmaxf(tm0, __shfl_xor_sync(0xffffffffu, tm0, 2));
        tm1 = fmaxf(tm1, __shfl_xor_sync(0xffffffffu, tm1, 1));
        tm1 = fmaxf(tm1, __shfl_xor_sync(0xffffffffu, tm1, 2));
        float mn0 = fmaxf(m0, tm0), mn1 = fmaxf(m1, tm1);
        float cr0 = __expf(m0 - mn0), cr1 = __expf(m1 - mn1);
        m0 = mn0; m1 = mn1;
        l0 *= cr0; l1 *= cr1;
#pragma unroll
        for (int f = 0; f < 8; f++) {
            oacc[f][0] *= cr0; oacc[f][1] *= cr0;
            oacc[f][2] *= cr1; oacc[f][3] *= cr1;
        }

        uint32_t ph[8][4], pl[8][4];
#pragma unroll
        for (int j = 0; j < 16; j++) {
            float p0 = __expf(sacc[j][0] - m0);
            float p1 = __expf(sacc[j][1] - m0);
            float p2 = __expf(sacc[j][2] - m1);
            float p3 = __expf(sacc[j][3] - m1);
            l0 += p0 + p1;
            l1 += p2 + p3;
            uint32_t hA = pack_bf16x2(p0, p1);
            uint32_t hB = pack_bf16x2(p2, p3);
            uint32_t lA = pack_bf16x2(p0 - bf16x2_lo(hA), p1 - bf16x2_hi(hA));
            uint32_t lB = pack_bf16x2(p2 - bf16x2_lo(hB), p3 - bf16x2_hi(hB));
            int kv = j >> 1, o = (j & 1) * 2;
            ph[kv][o] = hA; ph[kv][o + 1] = hB;
            pl[kv][o] = lA; pl[kv][o + 1] = lB;
        }

        // ---- O += Ph*Vh + Pl*Vh + Ph*Vl ----
#pragma unroll
        for (int kv = 0; kv < 8; kv++) {
#pragma unroll
            for (int nb = 0; nb < 4; nb++) {
                uint32_t vh[4], vl[4];
                int vr = kv * 16 + (((lane >> 3) & 1) << 3) + (lane & 7);
                int vc = nb * 16 + ((lane >> 4) << 3);
                uint32_t so = sw128(vr * 128 + vc * 2);
                ldm_x4_t(vh, sVh + so);
                ldm_x4_t(vl, sVl + so);
                mma_bf16(oacc[2 * nb],     ph[kv], vh);
                mma_bf16(oacc[2 * nb + 1], ph[kv], vh + 2);
                mma_bf16(oacc[2 * nb],     pl[kv], vh);
                mma_bf16(oacc[2 * nb + 1], pl[kv], vh + 2);
                mma_bf16(oacc[2 * nb],     ph[kv], vl);
                mma_bf16(oacc[2 * nb + 1], ph[kv], vl + 2);
            }
        }
    }

    // reduce row sums across quad lanes
    l0 += __shfl_xor_sync(0xffffffffu, l0, 1);
    l0 += __shfl_xor_sync(0xffffffffu, l0, 2);
    l1 += __shfl_xor_sync(0xffffffffu, l1, 1);
    l1 += __shfl_xor_sync(0xffffffffu, l1, 2);
    float inv0 = 1.f / l0, inv1 = 1.f / l1;

    // write O (normalized, split hi/lo) to g_o2 [row][2048]
    size_t r0g = (size_t)(b * TT + qb * 64 + w * 16 + (lane >> 2));
    size_t r1g = r0g + 8;
    int colb = h * HD + 2 * (lane & 3);
#pragma unroll
    for (int f = 0; f < 8; f++) {
        int col = colb + f * 8;
        float v00 = oacc[f][0] * inv0, v01 = oacc[f][1] * inv0;
        float v10 = oacc[f][2] * inv1, v11 = oacc[f][3] * inv1;
        uint32_t h0 = pack_bf16x2(v00, v01);
        uint32_t h1 = pack_bf16x2(v10, v11);
        *(uint32_t*)(g_o2 + r0g * 2048 + col) = h0;
        *(uint32_t*)(g_o2 + r1g * 2048 + col) = h1;
        *(uint32_t*)(g_o2 + r0g * 2048 + 1024 + col) =
            pack_bf16x2(v00 - bf16x2_lo(h0), v01 - bf16x2_hi(h0));
        *(uint32_t*)(g_o2 + r1g * 2048 + 1024 + col) =
            pack_bf16x2(v10 - bf16x2_lo(h1), v11 - bf16x2_hi(h1));
    }
}

// ---------------------------------------------------------------------------
extern "C" void kernel_launch(void* const* d_in, const int* in_sizes, int n_in,
                              void* d_out, int out_size)
{
    const float* x  = (const float*)d_in[0];
    const float* Wq = (const float*)d_in[1];
    const float* Wk = (const float*)d_in[2];
    const float* Wv = (const float*)d_in[3];
    const float* Wu = (const float*)d_in[4];
    const float* bu = (const float*)d_in[5];
    float* out = (float*)d_out;

    split_kernel<<<MTOT, 256>>>(x,  0);
    split_kernel<<<KD,   256>>>(Wq, 1);
    split_kernel<<<KD,   256>>>(Wk, 2);
    split_kernel<<<KD,   256>>>(Wv, 3);
    split_kernel<<<KD,   256>>>(Wu, 4);

    cudaFuncSetAttribute(qkv_mma, cudaFuncAttributeMaxDynamicSharedMemorySize, SMEM_MMA);
    qkv_mma<<<dim3(KD / 128, MTOT / 128, 3), 256, SMEM_MMA>>>();

    cudaFuncSetAttribute(attn_mma, cudaFuncAttributeMaxDynamicSharedMemorySize, ATT_SMEM);
    attn_mma<<<dim3(TT / 64, NH, BB), 128, ATT_SMEM>>>();

    cudaFuncSetAttribute(out_mma, cudaFuncAttributeMaxDynamicSharedMemorySize, SMEM_MMA);
    out_mma<<<dim3(KD / 128, MTOT / 128), 256, SMEM_MMA>>>(bu, out);
}

// round 5
// speedup vs baseline: 6.5470x; 2.1848x over previous
#include <cuda_runtime.h>
#include <cuda_fp16.h>
#include <math_constants.h>
#include <cstdint>

#define BB   2
#define TT   2048
#define KD   1024
#define NH   16
#define HD   64
#define MTOT (BB*TT)

// ---------------- scratch (__device__ globals, allocation-free) -------------
__device__ __half g_xh [(size_t)MTOT * KD];
__device__ __half g_wqh[(size_t)KD   * KD];
__device__ __half g_wkh[(size_t)KD   * KD];
__device__ __half g_wvh[(size_t)KD   * KD];
__device__ __half g_wuh[(size_t)KD   * KD];
__device__ __half g_qh [(size_t)MTOT * KD];
__device__ __half g_kh [(size_t)MTOT * KD];
__device__ __half g_vh [(size_t)MTOT * KD];
__device__ __half g_oh [(size_t)MTOT * KD];

// ---------------- helpers ----------------------------------------------------
__device__ __forceinline__ uint32_t smem_u32(const void* p) {
    uint32_t a;
    asm("{ .reg .u64 t; cvta.to.shared.u64 t, %1; cvt.u32.u64 %0, t; }"
        : "=r"(a) : "l"(p));
    return a;
}
__device__ __forceinline__ void cp16(uint32_t dst, const void* src) {
    asm volatile("cp.async.cg.shared.global [%0], [%1], 16;" :: "r"(dst), "l"(src));
}
__device__ __forceinline__ void cp_commit() {
    asm volatile("cp.async.commit_group;" ::: "memory");
}
template <int N>
__device__ __forceinline__ void cp_wait() {
    asm volatile("cp.async.wait_group %0;" :: "n"(N) : "memory");
}
__device__ __forceinline__ void ldm_x4(uint32_t* r, uint32_t addr) {
    asm volatile("ldmatrix.sync.aligned.m8n8.x4.shared.b16 {%0,%1,%2,%3}, [%4];"
                 : "=r"(r[0]), "=r"(r[1]), "=r"(r[2]), "=r"(r[3]) : "r"(addr));
}
__device__ __forceinline__ void ldm_x4_t(uint32_t* r, uint32_t addr) {
    asm volatile("ldmatrix.sync.aligned.m8n8.x4.trans.shared.b16 {%0,%1,%2,%3}, [%4];"
                 : "=r"(r[0]), "=r"(r[1]), "=r"(r[2]), "=r"(r[3]) : "r"(addr));
}
__device__ __forceinline__ void mma_f16(float* c, const uint32_t* a, const uint32_t* b) {
    asm volatile(
        "mma.sync.aligned.m16n8k16.row.col.f32.f16.f16.f32 "
        "{%0,%1,%2,%3}, {%4,%5,%6,%7}, {%8,%9}, {%0,%1,%2,%3};"
        : "+f"(c[0]), "+f"(c[1]), "+f"(c[2]), "+f"(c[3])
        : "r"(a[0]), "r"(a[1]), "r"(a[2]), "r"(a[3]), "r"(b[0]), "r"(b[1]));
}
__device__ __forceinline__ uint32_t pack_h2(float a, float b) {
    __half2 h = __floats2half2_rn(a, b);
    return *(uint32_t*)&h;
}
__device__ __forceinline__ uint32_t sw128(uint32_t off) {
    return off ^ ((off >> 3) & 0x70);
}

// ---------------- fused fp32 -> fp16 conversion ------------------------------
__global__ void cvt_kernel(const float* __restrict__ x,  const float* __restrict__ wq,
                           const float* __restrict__ wk, const float* __restrict__ wv,
                           const float* __restrict__ wu)
{
    const int which = blockIdx.y;
    const float* in;
    __half* out;
    int rows;
    switch (which) {
        case 0: in = x;  out = g_xh;  rows = MTOT; break;
        case 1: in = wq; out = g_wqh; rows = KD;   break;
        case 2: in = wk; out = g_wkh; rows = KD;   break;
        case 3: in = wv; out = g_wvh; rows = KD;   break;
        default: in = wu; out = g_wuh; rows = KD;  break;
    }
    int r = blockIdx.x;
    if (r >= rows) return;
    int c = threadIdx.x * 4;
    float4 a = *(const float4*)(in + (size_t)r * KD + c);
    uint2 o;
    o.x = pack_h2(a.x, a.y);
    o.y = pack_h2(a.z, a.w);
    *(uint2*)(out + (size_t)r * KD + c) = o;
}

// ---------------- mma.sync fp16 GEMM ------------------------------------------
// C[m,n] = scale * sum_k A[m,k]*W[n,k]
// mode 0: fp32 out + bias;  mode 1: fp16 out
#define GSTRIDE 40
#define STAGE_B (128 * GSTRIDE * 2)
#define SMEM_MMA (4 * STAGE_B)

__device__ __forceinline__ void load_stage(
    const __half* __restrict__ Ag, const __half* __restrict__ Wg,
    uint32_t sA, uint32_t sB, int tid)
{
#pragma unroll
    for (int i = 0; i < 2; i++) {
        int c = tid + i * 256;
        int r = c >> 2;
        int q = c & 3;
        cp16(sA + r * (GSTRIDE * 2) + q * 16, Ag + (size_t)r * KD + q * 8);
        cp16(sB + r * (GSTRIDE * 2) + q * 16, Wg + (size_t)r * KD + q * 8);
    }
}

__device__ __forceinline__ void tgemm_mma(
    const __half* __restrict__ A2, const __half* __restrict__ W2,
    float scale, int mode,
    float* __restrict__ Cf, const float* __restrict__ bias,
    __half* __restrict__ Ch)
{
    extern __shared__ char sm[];
    const uint32_t smb = smem_u32(sm);
    const int tid    = threadIdx.x;
    const int lane   = tid & 31;
    const int wid    = tid >> 5;
    const int warp_m = wid & 1;
    const int warp_n = wid >> 1;
    const int m0     = blockIdx.y * 128;
    const int n0     = blockIdx.x * 128;

    const __half* Abase = A2 + (size_t)m0 * KD;
    const __half* Wbase = W2 + (size_t)n0 * KD;

    float acc[4][4][4];
#pragma unroll
    for (int i = 0; i < 4; i++)
#pragma unroll
        for (int j = 0; j < 4; j++)
#pragma unroll
            for (int r = 0; r < 4; r++) acc[i][j][r] = 0.f;

    const int NIT = 32;

    load_stage(Abase, Wbase, smb, smb + STAGE_B, tid);
    cp_commit();

    const int a_row = (lane & 15);
    const int a_col = (lane >> 4) << 3;
    const int b_row = ((lane >> 4) << 3) + (lane & 7);
    const int b_col = ((lane >> 3) & 1) << 3;

    for (int it = 0; it < NIT; it++) {
        const int s = it & 1;
        if (it + 1 < NIT) {
            const int kk = (it + 1) * 32;
            load_stage(Abase + kk, Wbase + kk,
                       smb + (((it + 1) & 1) ? 2 : 0) * STAGE_B,
                       smb + (((it + 1) & 1) ? 3 : 1) * STAGE_B, tid);
            cp_commit();
            cp_wait<1>();
        } else {
            cp_wait<0>();
        }
        __syncthreads();

        const uint32_t sA = smb + (s ? 2 : 0) * STAGE_B;
        const uint32_t sB = smb + (s ? 3 : 1) * STAGE_B;

#pragma unroll
        for (int ks = 0; ks < 2; ks++) {
            uint32_t a[4][4], b[2][4];
#pragma unroll
            for (int mi = 0; mi < 4; mi++)
                ldm_x4(a[mi], sA + (warp_m * 64 + mi * 16 + a_row) * (GSTRIDE * 2)
                              + (ks * 16 + a_col) * 2);
#pragma unroll
            for (int ni = 0; ni < 2; ni++)
                ldm_x4(b[ni], sB + (warp_n * 32 + ni * 16 + b_row) * (GSTRIDE * 2)
                              + (ks * 16 + b_col) * 2);
#pragma unroll
            for (int mi = 0; mi < 4; mi++)
#pragma unroll
                for (int nj = 0; nj < 4; nj++)
                    mma_f16(acc[mi][nj], a[mi], &b[nj >> 1][(nj & 1) * 2]);
        }
        __syncthreads();
    }

#pragma unroll
    for (int mi = 0; mi < 4; mi++) {
#pragma unroll
        for (int nj = 0; nj < 4; nj++) {
            int row = m0 + warp_m * 64 + mi * 16 + (lane >> 2);
            int col = n0 + warp_n * 32 + nj * 8 + (lane & 3) * 2;
            float v00 = acc[mi][nj][0] * scale, v01 = acc[mi][nj][1] * scale;
            float v10 = acc[mi][nj][2] * scale, v11 = acc[mi][nj][3] * scale;
            if (mode == 0) {
                float b0 = bias[col], b1 = bias[col + 1];
                *(float2*)(Cf + (size_t)row * KD + col)       = make_float2(v00 + b0, v01 + b1);
                *(float2*)(Cf + (size_t)(row + 8) * KD + col) = make_float2(v10 + b0, v11 + b1);
            } else {
                *(uint32_t*)(Ch + (size_t)row * KD + col)       = pack_h2(v00, v01);
                *(uint32_t*)(Ch + (size_t)(row + 8) * KD + col) = pack_h2(v10, v11);
            }
        }
    }
}

__global__ __launch_bounds__(256, 2) void qkv_mma() {
    const float inv_s = 0.17677669529663687f;   // 1024^(-1/4)
    if (blockIdx.z == 0)
        tgemm_mma(g_xh, g_wqh, inv_s, 1, nullptr, nullptr, g_qh);
    else if (blockIdx.z == 1)
        tgemm_mma(g_xh, g_wkh, inv_s, 1, nullptr, nullptr, g_kh);
    else
        tgemm_mma(g_xh, g_wvh, 1.0f, 1, nullptr, nullptr, g_vh);
}

__global__ __launch_bounds__(256, 2) void out_mma(const float* __restrict__ bu,
                                                  float* __restrict__ out) {
    tgemm_mma(g_oh, g_wuh, 1.0f, 0, out, bu, nullptr);
}

// ---------------- tensorized flash attention (fp16, single combo) ------------
// CTA: 64 q-rows x (head, batch). 4 warps, 16 rows each, full 128 S-cols/warp.
#define ATT_STAGE 32768                       // K 16K + V 16K
#define ATT_SMEM  (8192 + 2 * ATT_STAGE)      // 73728

__global__ __launch_bounds__(128, 2) void attn_mma()
{
    extern __shared__ char sm[];
    const uint32_t smb = smem_u32(sm);
    const int tid = threadIdx.x, lane = tid & 31, w = tid >> 5;
    const int qb = blockIdx.x, h = blockIdx.y, b = blockIdx.z;

    const __half* Qg = g_qh + (size_t)(b * TT + qb * 64) * KD + h * HD;
    const __half* Kg = g_kh + (size_t)(b * TT) * KD + h * HD;
    const __half* Vg = g_vh + (size_t)(b * TT) * KD + h * HD;

    const uint32_t sQ = smb;

    // Q: 64 rows x 128B = 512 chunks
#pragma unroll
    for (int i = 0; i < 4; i++) {
        int c = tid + i * 128, r = c >> 3, q = c & 7;
        cp16(sQ + sw128(r * 128 + q * 16), Qg + (size_t)r * KD + q * 8);
    }
    // stage 0: K, V
    {
        uint32_t sK = smb + 8192;
#pragma unroll
        for (int i = 0; i < 8; i++) {
            int c = tid + i * 128, r = c >> 3, q = c & 7;
            uint32_t so = sw128(r * 128 + q * 16);
            size_t   go = (size_t)r * KD + q * 8;
            cp16(sK + so,         Kg + go);
            cp16(sK + 16384 + so, Vg + go);
        }
    }
    cp_commit();

    float oacc[8][4];
#pragma unroll
    for (int f = 0; f < 8; f++)
#pragma unroll
        for (int r = 0; r < 4; r++) oacc[f][r] = 0.f;
    float m0 = -CUDART_INF_F, m1 = -CUDART_INF_F, l0 = 0.f, l1 = 0.f;
    uint32_t qa[4][4];

    for (int jb = 0; jb < TT / 128; jb++) {
        cp_wait<0>();
        __syncthreads();

        if (jb + 1 < TT / 128) {
            uint32_t sK = smb + 8192 + ((jb + 1) & 1) * ATT_STAGE;
            size_t base = (size_t)(jb + 1) * 128;
#pragma unroll
            for (int i = 0; i < 8; i++) {
                int c = tid + i * 128, r = c >> 3, q = c & 7;
                uint32_t so = sw128(r * 128 + q * 16);
                size_t   go = (base + r) * KD + q * 8;
                cp16(sK + so,         Kg + go);
                cp16(sK + 16384 + so, Vg + go);
            }
            cp_commit();
        }

        if (jb == 0) {
#pragma unroll
            for (int ks = 0; ks < 4; ks++) {
                int ar = w * 16 + (lane & 15);
                int ac = ks * 16 + ((lane >> 4) << 3);
                ldm_x4(qa[ks], sQ + sw128(ar * 128 + ac * 2));
            }
        }

        const uint32_t sK = smb + 8192 + (jb & 1) * ATT_STAGE;
        const uint32_t sV = sK + 16384;

        // ---- S = Q * K^T ----
        float sacc[16][4];
#pragma unroll
        for (int j = 0; j < 16; j++)
#pragma unroll
            for (int r = 0; r < 4; r++) sacc[j][r] = 0.f;

#pragma unroll
        for (int ks = 0; ks < 4; ks++) {
#pragma unroll
            for (int jn = 0; jn < 8; jn++) {
                uint32_t kb[4];
                int br = jn * 16 + ((lane >> 4) << 3) + (lane & 7);
                int bc = ks * 16 + (((lane >> 3) & 1) << 3);
                ldm_x4(kb, sK + sw128(br * 128 + bc * 2));
                mma_f16(sacc[2 * jn],     qa[ks], kb);
                mma_f16(sacc[2 * jn + 1], qa[ks], kb + 2);
            }
        }

        // ---- online softmax ----
        float tm0 = -CUDART_INF_F, tm1 = -CUDART_INF_F;
#pragma unroll
        for (int j = 0; j < 16; j++) {
            tm0 = fmaxf(tm0, fmaxf(sacc[j][0], sacc[j][1]));
            tm1 = fmaxf(tm1, fmaxf(sacc[j][2], sacc[j][3]));
        }
        tm0 = fmaxf(tm0, __shfl_xor_sync(0xffffffffu, tm0, 1));
        tm0 = fmaxf(tm0, __shfl_xor_sync(0xffffffffu, tm0, 2));
        tm1 = fmaxf(tm1, __shfl_xor_sync(0xffffffffu, tm1, 1));
        tm1 = fmaxf(tm1, __shfl_xor_sync(0xffffffffu, tm1, 2));
        float mn0 = fmaxf(m0, tm0), mn1 = fmaxf(m1, tm1);
        float cr0 = __expf(m0 - mn0), cr1 = __expf(m1 - mn1);
        m0 = mn0; m1 = mn1;
        l0 *= cr0; l1 *= cr1;
#pragma unroll
        for (int f = 0; f < 8; f++) {
            oacc[f][0] *= cr0; oacc[f][1] *= cr0;
            oacc[f][2] *= cr1; oacc[f][3] *= cr1;
        }

        uint32_t ph[8][4];
#pragma unroll
        for (int j = 0; j < 16; j++) {
            float p0 = __expf(sacc[j][0] - m0);
            float p1 = __expf(sacc[j][1] - m0);
            float p2 = __expf(sacc[j][2] - m1);
            float p3 = __expf(sacc[j][3] - m1);
            uint32_t hA = pack_h2(p0, p1);
            uint32_t hB = pack_h2(p2, p3);
            // accumulate l from the ROUNDED values so num/denom rounding cancels
            __half2 rA = *(__half2*)&hA, rB = *(__half2*)&hB;
            float2 fA = __half22float2(rA), fB = __half22float2(rB);
            l0 += fA.x + fA.y;
            l1 += fB.x + fB.y;
            int kv = j >> 1, o = (j & 1) * 2;
            ph[kv][o] = hA; ph[kv][o + 1] = hB;
        }

        // ---- O += P * V ----
#pragma unroll
        for (int kv = 0; kv < 8; kv++) {
#pragma unroll
            for (int nb = 0; nb < 4; nb++) {
                uint32_t vb[4];
                int vr = kv * 16 + (((lane >> 3) & 1) << 3) + (lane & 7);
                int vc = nb * 16 + ((lane >> 4) << 3);
                ldm_x4_t(vb, sV + sw128(vr * 128 + vc * 2));
                mma_f16(oacc[2 * nb],     ph[kv], vb);
                mma_f16(oacc[2 * nb + 1], ph[kv], vb + 2);
            }
        }
    }

    l0 += __shfl_xor_sync(0xffffffffu, l0, 1);
    l0 += __shfl_xor_sync(0xffffffffu, l0, 2);
    l1 += __shfl_xor_sync(0xffffffffu, l1, 1);
    l1 += __shfl_xor_sync(0xffffffffu, l1, 2);
    float inv0 = 1.f / l0, inv1 = 1.f / l1;

    size_t r0g = (size_t)(b * TT + qb * 64 + w * 16 + (lane >> 2));
    size_t r1g = r0g + 8;
    int colb = h * HD + 2 * (lane & 3);
#pragma unroll
    for (int f = 0; f < 8; f++) {
        int col = colb + f * 8;
        *(uint32_t*)(g_oh + r0g * KD + col) = pack_h2(oacc[f][0] * inv0, oacc[f][1] * inv0);
        *(uint32_t*)(g_oh + r1g * KD + col) = pack_h2(oacc[f][2] * inv1, oacc[f][3] * inv1);
    }
}

// ---------------------------------------------------------------------------
extern "C" void kernel_launch(void* const* d_in, const int* in_sizes, int n_in,
                              void* d_out, int out_size)
{
    const float* x  = (const float*)d_in[0];
    const float* Wq = (const float*)d_in[1];
    const float* Wk = (const float*)d_in[2];
    const float* Wv = (const float*)d_in[3];
    const float* Wu = (const float*)d_in[4];
    const float* bu = (const float*)d_in[5];
    float* out = (float*)d_out;

    cvt_kernel<<<dim3(MTOT, 5), 256>>>(x, Wq, Wk, Wv, Wu);

    cudaFuncSetAttribute(qkv_mma, cudaFuncAttributeMaxDynamicSharedMemorySize, SMEM_MMA);
    qkv_mma<<<dim3(KD / 128, MTOT / 128, 3), 256, SMEM_MMA>>>();

    cudaFuncSetAttribute(attn_mma, cudaFuncAttributeMaxDynamicSharedMemorySize, ATT_SMEM);
    attn_mma<<<dim3(TT / 64, NH, BB), 128, ATT_SMEM>>>();

    cudaFuncSetAttribute(out_mma, cudaFuncAttributeMaxDynamicSharedMemorySize, SMEM_MMA);
    out_mma<<<dim3(KD / 128, MTOT / 128), 256, SMEM_MMA>>>(bu, out);
}